// round 2
// baseline (speedup 1.0000x reference)
#include <cuda_runtime.h>
#include <cuda_bf16.h>

// binary contrastive loss:
//   sim0[i] = <x[i],x[i]>/temp ; sim1[i] = <x[i],x[samples[i]]>/temp
//   diff = sim0-sim1 ; label = (y[i]!=y[samples[i]])
//   loss = -log(sigmoid(diff)+eps)*label - log(1-sigmoid(diff)+eps)*(1-label)
//   out  = mean(loss)
//
// x: [B=16384, D=2048] fp32 ; y, samples: int32 (JAX x64 disabled -> int64
// request silently becomes int32) ; out: 1 fp32 scalar.
// HBM-bound: ~256MB of reads. One block per row, float4 loads, block reduce,
// atomicAdd of per-row loss into a device accumulator, finalize divides by B.

#define TEMP_INV 10.0f
#define EPS 1e-5f

__device__ float g_accum;

__global__ void zero_kernel() {
    if (threadIdx.x == 0) g_accum = 0.0f;
}

__global__ __launch_bounds__(256) void loss_kernel(
    const float* __restrict__ x,
    const int* __restrict__ y,
    const int* __restrict__ samples,
    int B, int D)
{
    const int i = blockIdx.x;
    const int j = samples[i];

    const float4* __restrict__ xi = reinterpret_cast<const float4*>(x + (size_t)i * D);
    const float4* __restrict__ xj = reinterpret_cast<const float4*>(x + (size_t)j * D);

    float s0 = 0.0f, s1 = 0.0f;
    const int nvec = D >> 2;  // 512 float4 per row

    // 256 threads -> 2 iterations; unrolled for MLP
    #pragma unroll 2
    for (int t = threadIdx.x; t < nvec; t += blockDim.x) {
        float4 a = xi[t];
        float4 b = xj[t];
        s0 = fmaf(a.x, a.x, s0); s0 = fmaf(a.y, a.y, s0);
        s0 = fmaf(a.z, a.z, s0); s0 = fmaf(a.w, a.w, s0);
        s1 = fmaf(a.x, b.x, s1); s1 = fmaf(a.y, b.y, s1);
        s1 = fmaf(a.z, b.z, s1); s1 = fmaf(a.w, b.w, s1);
    }

    // warp reduce
    #pragma unroll
    for (int o = 16; o > 0; o >>= 1) {
        s0 += __shfl_xor_sync(0xFFFFFFFFu, s0, o);
        s1 += __shfl_xor_sync(0xFFFFFFFFu, s1, o);
    }

    __shared__ float sh0[8], sh1[8];
    const int w = threadIdx.x >> 5;
    const int l = threadIdx.x & 31;
    if (l == 0) { sh0[w] = s0; sh1[w] = s1; }
    __syncthreads();

    if (threadIdx.x == 0) {
        #pragma unroll
        for (int k = 1; k < 8; k++) { s0 += sh0[k]; s1 += sh1[k]; }

        const float diff = (s0 - s1) * TEMP_INV;
        const float p = 1.0f / (1.0f + expf(-diff));
        const float label = (y[i] != y[j]) ? 1.0f : 0.0f;
        const float loss = -logf(p + EPS) * label
                           - logf(1.0f - p + EPS) * (1.0f - label);
        atomicAdd(&g_accum, loss);
    }
}

__global__ void finalize_kernel(float* __restrict__ out, float invB) {
    if (threadIdx.x == 0) out[0] = g_accum * invB;
}

extern "C" void kernel_launch(void* const* d_in, const int* in_sizes, int n_in,
                              void* d_out, int out_size)
{
    const float* x       = (const float*)d_in[0];
    const int*   y       = (const int*)d_in[1];
    const int*   samples = (const int*)d_in[2];
    float* out = (float*)d_out;

    const int B = in_sizes[1];                 // 16384
    const int D = in_sizes[0] / in_sizes[1];   // 2048

    zero_kernel<<<1, 32>>>();
    loss_kernel<<<B, 256>>>(x, y, samples, B, D);
    finalize_kernel<<<1, 32>>>(out, 1.0f / (float)B);
}